// round 1
// baseline (speedup 1.0000x reference)
#include <cuda_runtime.h>
#include <math.h>

#define NUM_RANGES 256
#define KPR 512
#define DOPPLER 64
#define EMBED 16
#define IN_DIM 96
#define NROWS (NUM_RANGES * KPR)   // 131072

// Scratch (static device allocations are permitted)
__device__ float g_Q[NROWS * DOPPLER];
__device__ float g_K[NROWS * DOPPLER];
__device__ float g_vs[NROWS];

// ---------------------------------------------------------------------------
// Kernel A: fused gather + QK projection (+ vsum)
// CTA: 256 threads, 128 rows. smem GEMM [128x96] @ [96x128] (cols 0..63 = Q, 64..127 = K)
// ---------------------------------------------------------------------------
#define A_ROWS 128
#define A_PAD 132   // 132 % 32 == 4 -> 4-way conflicts on transpose writes, float4-aligned rows
#define A_SMEM_FLOATS (2 * 96 * A_PAD + 96 + 128 + 4)
#define A_SMEM_BYTES (A_SMEM_FLOATS * 4)

__global__ void __launch_bounds__(256, 2) qkv_kernel(
    const float* __restrict__ power, const int* __restrict__ ele_idx,
    const int* __restrict__ azi_idx, const float* __restrict__ ele_tab,
    const float* __restrict__ azi_tab,
    const float* __restrict__ Wq, const float* __restrict__ bq,
    const float* __restrict__ Wk, const float* __restrict__ bk,
    const float* __restrict__ Wv, const float* __restrict__ bv)
{
    extern __shared__ float sm[];
    float* sX   = sm;                    // [96][A_PAD]  x^T (f-major)
    float* sW   = sm + 96 * A_PAD;       // [96][A_PAD]  W^T (f-major), cols 0..63 Wq, 64..127 Wk
    float* sWv  = sm + 2 * 96 * A_PAD;   // [96] column sums of Wv
    float* sB   = sWv + 96;              // [128] bq|bk
    float* sBvs = sB + 128;              // [1] sum(bv)

    const int tid  = threadIdx.x;
    const int row0 = blockIdx.x * A_ROWS;

    // power -> sX (coalesced gmem read, 4-way-conflict smem transpose write)
    for (int i = tid; i < A_ROWS * DOPPLER; i += 256) {
        int r = i >> 6, f = i & 63;
        sX[f * A_PAD + r] = power[(row0 + r) * DOPPLER + f];
    }
    // embedding gathers -> sX rows 64..95
    for (int i = tid; i < A_ROWS * 2 * EMBED; i += 256) {
        int r = i >> 5, e = i & 31;
        int row = row0 + r;
        float v; int f;
        if (e < EMBED) { v = ele_tab[ele_idx[row] * EMBED + e];          f = 64 + e; }
        else           { v = azi_tab[azi_idx[row] * EMBED + (e - EMBED)]; f = 80 + (e - EMBED); }
        sX[f * A_PAD + r] = v;
    }
    // weights (transposed to f-major)
    for (int i = tid; i < 64 * 96; i += 256) {
        int d = i / 96, f = i % 96;
        sW[f * A_PAD + d]      = Wq[i];
        sW[f * A_PAD + 64 + d] = Wk[i];
    }
    if (tid < 96) {
        float s = 0.f;
        #pragma unroll 8
        for (int d = 0; d < 64; ++d) s += Wv[d * 96 + tid];
        sWv[tid] = s;
    }
    if (tid < 64)       sB[tid] = bq[tid];
    else if (tid < 128) sB[tid] = bk[tid - 64];
    if (tid == 0) {
        float s = 0.f;
        #pragma unroll 8
        for (int d = 0; d < 64; ++d) s += bv[d];
        *sBvs = s;
    }
    __syncthreads();

    // vsum for the 128 rows (threads 0..127)
    if (tid < 128) {
        float acc = *sBvs;
        #pragma unroll 4
        for (int f = 0; f < 96; ++f) acc += sX[f * A_PAD + tid] * sWv[f];
        g_vs[row0 + tid] = acc;
    }

    // 128x128 register-blocked GEMM: thread (ty,tx) computes rows ty*8..+8, cols tx*8..+8
    const int ty = tid >> 4, tx = tid & 15;
    float acc[8][8];
    #pragma unroll
    for (int i = 0; i < 8; ++i)
        #pragma unroll
        for (int j = 0; j < 8; ++j) acc[i][j] = 0.f;

    #pragma unroll 2
    for (int f = 0; f < 96; ++f) {
        const float4* xr = (const float4*)(sX + f * A_PAD);
        const float4* wr = (const float4*)(sW + f * A_PAD);
        float4 a0 = xr[ty * 2], a1 = xr[ty * 2 + 1];
        float4 b0 = wr[tx * 2], b1 = wr[tx * 2 + 1];
        float a[8] = {a0.x, a0.y, a0.z, a0.w, a1.x, a1.y, a1.z, a1.w};
        float b[8] = {b0.x, b0.y, b0.z, b0.w, b1.x, b1.y, b1.z, b1.w};
        #pragma unroll
        for (int i = 0; i < 8; ++i)
            #pragma unroll
            for (int j = 0; j < 8; ++j) acc[i][j] += a[i] * b[j];
    }

    // epilogue: add bias, write Q (tx<8) or K (tx>=8)
    const int cbase = tx * 8;
    const bool isQ = (tx < 8);
    float* gout = isQ ? g_Q : g_K;
    const int cc = isQ ? cbase : (cbase - 64);
    float bb[8];
    #pragma unroll
    for (int j = 0; j < 8; ++j) bb[j] = sB[cbase + j];

    #pragma unroll
    for (int i = 0; i < 8; ++i) {
        int row = row0 + ty * 8 + i;
        float4 v0 = make_float4(acc[i][0] + bb[0], acc[i][1] + bb[1],
                                acc[i][2] + bb[2], acc[i][3] + bb[3]);
        float4 v1 = make_float4(acc[i][4] + bb[4], acc[i][5] + bb[5],
                                acc[i][6] + bb[6], acc[i][7] + bb[7]);
        *(float4*)&gout[row * 64 + cc]     = v0;
        *(float4*)&gout[row * 64 + cc + 4] = v1;
    }
}

// ---------------------------------------------------------------------------
// Kernel B: per half-range attention. grid = 512 (range = bid>>1, half = bid&1)
// smem: K^T [64][516] + Q [256][64]. Each warp: 16 q rows (4 at a time),
// lane owns 16 contiguous k. FMA-bound inner loop.
// ---------------------------------------------------------------------------
#define B_PAD 516   // 516 % 32 == 4; rows float4-aligned (516*4 = 2064 = 129*16)
#define B_SMEM_BYTES ((64 * B_PAD + 256 * 64) * 4)

__global__ void __launch_bounds__(512, 1) attn_kernel(float* __restrict__ out)
{
    extern __shared__ float sm[];
    float* sKT = sm;               // [64][B_PAD]
    float* sQ  = sm + 64 * B_PAD;  // [256][64]

    const int tid   = threadIdx.x;
    const int r     = blockIdx.x >> 1;
    const int h     = blockIdx.x & 1;
    const int kbase = r * KPR;
    const int qbase = kbase + h * 256;

    // K^T load (coalesced gmem, 4-way-conflict transpose write)
    for (int i = tid; i < KPR * 64; i += 512) {
        int k = i >> 6, d = i & 63;
        sKT[d * B_PAD + k] = g_K[(kbase + k) * 64 + d];
    }
    // Q tile (straight copy)
    for (int i = tid; i < 256 * 64; i += 512)
        sQ[i] = g_Q[qbase * 64 + i];
    __syncthreads();

    const int w = tid >> 5, lane = tid & 31;

    // this lane's 16 vsum values (reused for all q rows)
    float vs[16];
    #pragma unroll
    for (int u = 0; u < 4; ++u)
        *(float4*)&vs[u * 4] = *(const float4*)&g_vs[kbase + lane * 16 + u * 4];

    const float SC = 1.4426950408889634f * 0.125f;  // log2(e)/sqrt(64)

    for (int p = 0; p < 4; ++p) {
        const int q0 = w * 16 + p * 4;
        float s[4][16];
        #pragma unroll
        for (int qi = 0; qi < 4; ++qi)
            #pragma unroll
            for (int kk = 0; kk < 16; ++kk) s[qi][kk] = 0.f;

        const float* Qb = sQ + q0 * 64;

        #pragma unroll 2
        for (int d = 0; d < 64; ++d) {
            float kv[16];
            const float4* kr = (const float4*)(sKT + d * B_PAD) + lane * 4;
            #pragma unroll
            for (int u = 0; u < 4; ++u) *(float4*)&kv[u * 4] = kr[u];
            #pragma unroll
            for (int qi = 0; qi < 4; ++qi) {
                float qv = Qb[qi * 64 + d];  // broadcast LDS
                #pragma unroll
                for (int kk = 0; kk < 16; ++kk) s[qi][kk] += qv * kv[kk];
            }
        }

        #pragma unroll
        for (int qi = 0; qi < 4; ++qi) {
            float m = s[qi][0];
            #pragma unroll
            for (int kk = 1; kk < 16; ++kk) m = fmaxf(m, s[qi][kk]);
            #pragma unroll
            for (int o = 16; o > 0; o >>= 1)
                m = fmaxf(m, __shfl_xor_sync(0xffffffffu, m, o));

            float se = 0.f, sv = 0.f;
            #pragma unroll
            for (int kk = 0; kk < 16; ++kk) {
                float e = exp2f((s[qi][kk] - m) * SC);
                se += e;
                sv += e * vs[kk];
            }
            #pragma unroll
            for (int o = 16; o > 0; o >>= 1) {
                se += __shfl_xor_sync(0xffffffffu, se, o);
                sv += __shfl_xor_sync(0xffffffffu, sv, o);
            }
            if (lane == 0) out[qbase + q0 + qi] = sv / se;
        }
    }
}

// ---------------------------------------------------------------------------
// Launch
// ---------------------------------------------------------------------------
extern "C" void kernel_launch(void* const* d_in, const int* in_sizes, int n_in,
                              void* d_out, int out_size)
{
    const float* power   = (const float*)d_in[0];
    const int*   ele_idx = (const int*)  d_in[1];
    // d_in[2] = range_indices (unused by reference)
    const int*   azi_idx = (const int*)  d_in[3];
    const float* ele_tab = (const float*)d_in[4];
    const float* azi_tab = (const float*)d_in[5];
    const float* Wq      = (const float*)d_in[6];
    const float* bq      = (const float*)d_in[7];
    const float* Wk      = (const float*)d_in[8];
    const float* bk      = (const float*)d_in[9];
    const float* Wv      = (const float*)d_in[10];
    const float* bv      = (const float*)d_in[11];
    float* out = (float*)d_out;

    cudaFuncSetAttribute(qkv_kernel, cudaFuncAttributeMaxDynamicSharedMemorySize, A_SMEM_BYTES);
    cudaFuncSetAttribute(attn_kernel, cudaFuncAttributeMaxDynamicSharedMemorySize, B_SMEM_BYTES);

    qkv_kernel<<<NROWS / A_ROWS, 256, A_SMEM_BYTES>>>(
        power, ele_idx, azi_idx, ele_tab, azi_tab, Wq, bq, Wk, bk, Wv, bv);
    attn_kernel<<<NUM_RANGES * 2, 512, B_SMEM_BYTES>>>(out);
}

// round 2
// speedup vs baseline: 1.7789x; 1.7789x over previous
#include <cuda_runtime.h>
#include <math.h>

#define NUM_RANGES 256
#define KPR 512
#define DOPPLER 64
#define EMBED 16
#define IN_DIM 96
#define NROWS (NUM_RANGES * KPR)   // 131072

// Scratch (static device allocations are permitted)
__device__ float g_Q[NROWS * DOPPLER];
__device__ float g_K[NROWS * DOPPLER];
__device__ float g_vs[NROWS];

// ---------------------------------------------------------------------------
// Kernel A: fused gather + QK projection (+ vsum)
// CTA: 256 threads, 128 rows. smem GEMM [128x96] @ [96x128] (cols 0..63 = Q, 64..127 = K)
// ---------------------------------------------------------------------------
#define A_ROWS 128
#define A_PAD 132   // 132 % 32 == 4 -> 4-way conflicts on transpose writes, float4-aligned rows
#define A_SMEM_FLOATS (2 * 96 * A_PAD + 96 + 128 + 4)
#define A_SMEM_BYTES (A_SMEM_FLOATS * 4)

__global__ void __launch_bounds__(256, 2) qkv_kernel(
    const float* __restrict__ power, const int* __restrict__ ele_idx,
    const int* __restrict__ azi_idx, const float* __restrict__ ele_tab,
    const float* __restrict__ azi_tab,
    const float* __restrict__ Wq, const float* __restrict__ bq,
    const float* __restrict__ Wk, const float* __restrict__ bk,
    const float* __restrict__ Wv, const float* __restrict__ bv)
{
    extern __shared__ float sm[];
    float* sX   = sm;                    // [96][A_PAD]  x^T (f-major)
    float* sW   = sm + 96 * A_PAD;       // [96][A_PAD]  W^T (f-major), cols 0..63 Wq, 64..127 Wk
    float* sWv  = sm + 2 * 96 * A_PAD;   // [96] column sums of Wv
    float* sB   = sWv + 96;              // [128] bq|bk
    float* sBvs = sB + 128;              // [1] sum(bv)

    const int tid  = threadIdx.x;
    const int row0 = blockIdx.x * A_ROWS;

    // power -> sX (coalesced gmem read, 4-way-conflict smem transpose write)
    for (int i = tid; i < A_ROWS * DOPPLER; i += 256) {
        int r = i >> 6, f = i & 63;
        sX[f * A_PAD + r] = power[(row0 + r) * DOPPLER + f];
    }
    // embedding gathers -> sX rows 64..95
    for (int i = tid; i < A_ROWS * 2 * EMBED; i += 256) {
        int r = i >> 5, e = i & 31;
        int row = row0 + r;
        float v; int f;
        if (e < EMBED) { v = ele_tab[ele_idx[row] * EMBED + e];          f = 64 + e; }
        else           { v = azi_tab[azi_idx[row] * EMBED + (e - EMBED)]; f = 80 + (e - EMBED); }
        sX[f * A_PAD + r] = v;
    }
    // weights (transposed to f-major)
    for (int i = tid; i < 64 * 96; i += 256) {
        int d = i / 96, f = i % 96;
        sW[f * A_PAD + d]      = Wq[i];
        sW[f * A_PAD + 64 + d] = Wk[i];
    }
    if (tid < 96) {
        float s = 0.f;
        #pragma unroll 8
        for (int d = 0; d < 64; ++d) s += Wv[d * 96 + tid];
        sWv[tid] = s;
    }
    if (tid < 64)       sB[tid] = bq[tid];
    else if (tid < 128) sB[tid] = bk[tid - 64];
    if (tid == 0) {
        float s = 0.f;
        #pragma unroll 8
        for (int d = 0; d < 64; ++d) s += bv[d];
        *sBvs = s;
    }
    __syncthreads();

    // vsum for the 128 rows (threads 0..127)
    if (tid < 128) {
        float acc = *sBvs;
        #pragma unroll 4
        for (int f = 0; f < 96; ++f) acc += sX[f * A_PAD + tid] * sWv[f];
        g_vs[row0 + tid] = acc;
    }

    // 128x128 register-blocked GEMM: thread (ty,tx) computes rows ty*8..+8, cols tx*8..+8
    const int ty = tid >> 4, tx = tid & 15;
    float acc[8][8];
    #pragma unroll
    for (int i = 0; i < 8; ++i)
        #pragma unroll
        for (int j = 0; j < 8; ++j) acc[i][j] = 0.f;

    #pragma unroll 2
    for (int f = 0; f < 96; ++f) {
        const float4* xr = (const float4*)(sX + f * A_PAD);
        const float4* wr = (const float4*)(sW + f * A_PAD);
        float4 a0 = xr[ty * 2], a1 = xr[ty * 2 + 1];
        float4 b0 = wr[tx * 2], b1 = wr[tx * 2 + 1];
        float a[8] = {a0.x, a0.y, a0.z, a0.w, a1.x, a1.y, a1.z, a1.w};
        float b[8] = {b0.x, b0.y, b0.z, b0.w, b1.x, b1.y, b1.z, b1.w};
        #pragma unroll
        for (int i = 0; i < 8; ++i)
            #pragma unroll
            for (int j = 0; j < 8; ++j) acc[i][j] += a[i] * b[j];
    }

    // epilogue: add bias, write Q (tx<8) or K (tx>=8)
    const int cbase = tx * 8;
    const bool isQ = (tx < 8);
    float* gout = isQ ? g_Q : g_K;
    const int cc = isQ ? cbase : (cbase - 64);
    float bb[8];
    #pragma unroll
    for (int j = 0; j < 8; ++j) bb[j] = sB[cbase + j];

    #pragma unroll
    for (int i = 0; i < 8; ++i) {
        int row = row0 + ty * 8 + i;
        float4 v0 = make_float4(acc[i][0] + bb[0], acc[i][1] + bb[1],
                                acc[i][2] + bb[2], acc[i][3] + bb[3]);
        float4 v1 = make_float4(acc[i][4] + bb[4], acc[i][5] + bb[5],
                                acc[i][6] + bb[6], acc[i][7] + bb[7]);
        *(float4*)&gout[row * 64 + cc]     = v0;
        *(float4*)&gout[row * 64 + cc + 4] = v1;
    }
}

// ---------------------------------------------------------------------------
// Kernel B: per half-range attention. grid = 512 (range = bid>>1, half = bid&1)
// smem: K^T [64][516] + Q [256][64]. Each warp: 16 q rows (4 at a time).
// Lane owns k = {u*128 + lane*4 + j}  (u=0..3, j=0..3)  -> conflict-free LDS.128:
// word offset 128u + 4*lane -> banks (4d + 4*lane) mod 32, each 8-lane phase
// covers all 32 banks. FMA-bound inner loop.
// ---------------------------------------------------------------------------
#define B_PAD 516   // 516 % 32 == 4; rows float4-aligned (516*4 = 2064 = 129*16)
#define B_SMEM_BYTES ((64 * B_PAD + 256 * 64) * 4)

__global__ void __launch_bounds__(512, 1) attn_kernel(float* __restrict__ out)
{
    extern __shared__ float sm[];
    float* sKT = sm;               // [64][B_PAD]
    float* sQ  = sm + 64 * B_PAD;  // [256][64]

    const int tid   = threadIdx.x;
    const int r     = blockIdx.x >> 1;
    const int h     = blockIdx.x & 1;
    const int kbase = r * KPR;
    const int qbase = kbase + h * 256;

    // K^T load (coalesced gmem, 4-way-conflict transpose write)
    for (int i = tid; i < KPR * 64; i += 512) {
        int k = i >> 6, d = i & 63;
        sKT[d * B_PAD + k] = g_K[(kbase + k) * 64 + d];
    }
    // Q tile (straight copy)
    for (int i = tid; i < 256 * 64; i += 512)
        sQ[i] = g_Q[qbase * 64 + i];
    __syncthreads();

    const int w = tid >> 5, lane = tid & 31;

    // this lane's 16 vsum values: k = u*128 + lane*4 + j (coalesced float4 loads)
    float vs[16];
    #pragma unroll
    for (int u = 0; u < 4; ++u)
        *(float4*)&vs[u * 4] = *(const float4*)&g_vs[kbase + u * 128 + lane * 4];

    const float SC = 1.4426950408889634f * 0.125f;  // log2(e)/sqrt(64)

    for (int p = 0; p < 4; ++p) {
        const int q0 = w * 16 + p * 4;
        float s[4][16];
        #pragma unroll
        for (int qi = 0; qi < 4; ++qi)
            #pragma unroll
            for (int kk = 0; kk < 16; ++kk) s[qi][kk] = 0.f;

        const float* Qb = sQ + q0 * 64;

        #pragma unroll 2
        for (int d = 0; d < 64; ++d) {
            float kv[16];
            const float4* kr = (const float4*)(sKT + d * B_PAD);
            #pragma unroll
            for (int u = 0; u < 4; ++u)
                *(float4*)&kv[u * 4] = kr[u * 32 + lane];   // conflict-free
            #pragma unroll
            for (int qi = 0; qi < 4; ++qi) {
                float qv = Qb[qi * 64 + d];  // broadcast LDS
                #pragma unroll
                for (int kk = 0; kk < 16; ++kk) s[qi][kk] += qv * kv[kk];
            }
        }

        #pragma unroll
        for (int qi = 0; qi < 4; ++qi) {
            float m = s[qi][0];
            #pragma unroll
            for (int kk = 1; kk < 16; ++kk) m = fmaxf(m, s[qi][kk]);
            #pragma unroll
            for (int o = 16; o > 0; o >>= 1)
                m = fmaxf(m, __shfl_xor_sync(0xffffffffu, m, o));

            float se = 0.f, sv = 0.f;
            #pragma unroll
            for (int kk = 0; kk < 16; ++kk) {
                float e = exp2f((s[qi][kk] - m) * SC);
                se += e;
                sv += e * vs[kk];
            }
            #pragma unroll
            for (int o = 16; o > 0; o >>= 1) {
                se += __shfl_xor_sync(0xffffffffu, se, o);
                sv += __shfl_xor_sync(0xffffffffu, sv, o);
            }
            if (lane == 0) out[qbase + q0 + qi] = sv / se;
        }
    }
}

// ---------------------------------------------------------------------------
// Launch
// ---------------------------------------------------------------------------
extern "C" void kernel_launch(void* const* d_in, const int* in_sizes, int n_in,
                              void* d_out, int out_size)
{
    const float* power   = (const float*)d_in[0];
    const int*   ele_idx = (const int*)  d_in[1];
    // d_in[2] = range_indices (unused by reference)
    const int*   azi_idx = (const int*)  d_in[3];
    const float* ele_tab = (const float*)d_in[4];
    const float* azi_tab = (const float*)d_in[5];
    const float* Wq      = (const float*)d_in[6];
    const float* bq      = (const float*)d_in[7];
    const float* Wk      = (const float*)d_in[8];
    const float* bk      = (const float*)d_in[9];
    const float* Wv      = (const float*)d_in[10];
    const float* bv      = (const float*)d_in[11];
    float* out = (float*)d_out;

    cudaFuncSetAttribute(qkv_kernel, cudaFuncAttributeMaxDynamicSharedMemorySize, A_SMEM_BYTES);
    cudaFuncSetAttribute(attn_kernel, cudaFuncAttributeMaxDynamicSharedMemorySize, B_SMEM_BYTES);

    qkv_kernel<<<NROWS / A_ROWS, 256, A_SMEM_BYTES>>>(
        power, ele_idx, azi_idx, ele_tab, azi_tab, Wq, bq, Wk, bk, Wv, bv);
    attn_kernel<<<NUM_RANGES * 2, 512, B_SMEM_BYTES>>>(out);
}

// round 3
// speedup vs baseline: 2.1157x; 1.1893x over previous
#include <cuda_runtime.h>
#include <math.h>
#include <stdint.h>

#define NUM_RANGES 256
#define KPR 512
#define DOPPLER 64
#define EMBED 16
#define IN_DIM 96
#define NROWS (NUM_RANGES * KPR)   // 131072

// Scratch (static device allocations are permitted)
__device__ float g_Q[NROWS * DOPPLER];
__device__ float g_K[NROWS * DOPPLER];
__device__ float g_vs[NROWS];

// ---------------- packed fp32x2 helpers (Blackwell FFMA2) -------------------
__device__ __forceinline__ uint64_t splat2(float x) {
    uint64_t r; asm("mov.b64 %0, {%1, %1};" : "=l"(r) : "f"(x)); return r;
}
__device__ __forceinline__ void ffma2(uint64_t& d, uint64_t a, uint64_t b) {
    asm("fma.rn.f32x2 %0, %1, %2, %0;" : "+l"(d) : "l"(a), "l"(b));
}
__device__ __forceinline__ float lo32(uint64_t v) {
    return __uint_as_float((unsigned)(v & 0xffffffffu));
}
__device__ __forceinline__ float hi32(uint64_t v) {
    return __uint_as_float((unsigned)(v >> 32));
}

// ---------------------------------------------------------------------------
// Kernel A: fused gather + QK projection (+ vsum), FFMA2 mainloop
// CTA: 256 threads, 128 rows. smem GEMM [128x96] @ [96x128] (cols 0..63=Q, 64..127=K)
// ---------------------------------------------------------------------------
#define A_ROWS 128
#define A_PAD 132
#define A_SMEM_FLOATS (2 * 96 * A_PAD + 96 + 128 + 4)
#define A_SMEM_BYTES (A_SMEM_FLOATS * 4)

__global__ void __launch_bounds__(256, 2) qkv_kernel(
    const float* __restrict__ power, const int* __restrict__ ele_idx,
    const int* __restrict__ azi_idx, const float* __restrict__ ele_tab,
    const float* __restrict__ azi_tab,
    const float* __restrict__ Wq, const float* __restrict__ bq,
    const float* __restrict__ Wk, const float* __restrict__ bk,
    const float* __restrict__ Wv, const float* __restrict__ bv)
{
    extern __shared__ float sm[];
    float* sX   = sm;                    // [96][A_PAD]  x^T (f-major)
    float* sW   = sm + 96 * A_PAD;       // [96][A_PAD]  W^T (f-major)
    float* sWv  = sm + 2 * 96 * A_PAD;   // [96]
    float* sB   = sWv + 96;              // [128] bq|bk
    float* sBvs = sB + 128;              // [1]

    const int tid  = threadIdx.x;
    const int row0 = blockIdx.x * A_ROWS;

    for (int i = tid; i < A_ROWS * DOPPLER; i += 256) {
        int r = i >> 6, f = i & 63;
        sX[f * A_PAD + r] = power[(row0 + r) * DOPPLER + f];
    }
    for (int i = tid; i < A_ROWS * 2 * EMBED; i += 256) {
        int r = i >> 5, e = i & 31;
        int row = row0 + r;
        float v; int f;
        if (e < EMBED) { v = ele_tab[ele_idx[row] * EMBED + e];          f = 64 + e; }
        else           { v = azi_tab[azi_idx[row] * EMBED + (e - EMBED)]; f = 80 + (e - EMBED); }
        sX[f * A_PAD + r] = v;
    }
    for (int i = tid; i < 64 * 96; i += 256) {
        int d = i / 96, f = i % 96;
        sW[f * A_PAD + d]      = Wq[i];
        sW[f * A_PAD + 64 + d] = Wk[i];
    }
    if (tid < 96) {
        float s = 0.f;
        #pragma unroll 8
        for (int d = 0; d < 64; ++d) s += Wv[d * 96 + tid];
        sWv[tid] = s;
    }
    if (tid < 64)       sB[tid] = bq[tid];
    else if (tid < 128) sB[tid] = bk[tid - 64];
    if (tid == 0) {
        float s = 0.f;
        #pragma unroll 8
        for (int d = 0; d < 64; ++d) s += bv[d];
        *sBvs = s;
    }
    __syncthreads();

    if (tid < 128) {
        float acc = *sBvs;
        #pragma unroll 4
        for (int f = 0; f < 96; ++f) acc += sX[f * A_PAD + tid] * sWv[f];
        g_vs[row0 + tid] = acc;
    }

    // 128x128 register-blocked GEMM with packed FFMA2 (8 rows x 4 col-pairs)
    const int ty = tid >> 4, tx = tid & 15;
    uint64_t acc2[8][4];
    #pragma unroll
    for (int i = 0; i < 8; ++i)
        #pragma unroll
        for (int j = 0; j < 4; ++j) acc2[i][j] = 0ull;

    #pragma unroll 2
    for (int f = 0; f < 96; ++f) {
        const float4* xr = (const float4*)(sX + f * A_PAD);
        float4 a0 = xr[ty * 2], a1 = xr[ty * 2 + 1];
        float a[8] = {a0.x, a0.y, a0.z, a0.w, a1.x, a1.y, a1.z, a1.w};
        const ulonglong2* wr = (const ulonglong2*)(sW + f * A_PAD + tx * 8);
        ulonglong2 b0 = wr[0], b1 = wr[1];
        uint64_t bp[4] = {b0.x, b0.y, b1.x, b1.y};
        #pragma unroll
        for (int i = 0; i < 8; ++i) {
            uint64_t av = splat2(a[i]);
            #pragma unroll
            for (int jp = 0; jp < 4; ++jp) ffma2(acc2[i][jp], av, bp[jp]);
        }
    }

    // epilogue: unpack, add bias, write Q (tx<8) or K (tx>=8)
    const int cbase = tx * 8;
    const bool isQ = (tx < 8);
    float* gout = isQ ? g_Q : g_K;
    const int cc = isQ ? cbase : (cbase - 64);
    float bb[8];
    #pragma unroll
    for (int j = 0; j < 8; ++j) bb[j] = sB[cbase + j];

    #pragma unroll
    for (int i = 0; i < 8; ++i) {
        int row = row0 + ty * 8 + i;
        float4 v0 = make_float4(lo32(acc2[i][0]) + bb[0], hi32(acc2[i][0]) + bb[1],
                                lo32(acc2[i][1]) + bb[2], hi32(acc2[i][1]) + bb[3]);
        float4 v1 = make_float4(lo32(acc2[i][2]) + bb[4], hi32(acc2[i][2]) + bb[5],
                                lo32(acc2[i][3]) + bb[6], hi32(acc2[i][3]) + bb[7]);
        *(float4*)&gout[row * 64 + cc]     = v0;
        *(float4*)&gout[row * 64 + cc + 4] = v1;
    }
}

// ---------------------------------------------------------------------------
// Kernel B: per half-range attention, FFMA2 mainloop.
// grid = 512 (range = bid>>1, half = bid&1). CTA: 256 q rows, all 512 k.
// 16 warps = 8 q-groups x 2 k-halves. Warp: 8 q rows/pass (4 passes), 256 k
// (lane owns k = h*256 + u*128 + lane*4 + j, u<2, j<4 -> conflict-free LDS.128).
// Warp pairs combine partial softmax via smem logsumexp merge.
// ---------------------------------------------------------------------------
#define B_PAD 516
#define B_KT_FLOATS (64 * B_PAD)
#define B_Q_FLOATS (256 * 64)
#define B_COMB_FLOATS (256 * 2 * 4)
#define B_SMEM_BYTES ((B_KT_FLOATS + B_Q_FLOATS + B_COMB_FLOATS) * 4)

__global__ void __launch_bounds__(512, 1) attn_kernel(float* __restrict__ out)
{
    extern __shared__ float sm[];
    float* sKT   = sm;                            // [64][B_PAD]
    float* sQ    = sm + B_KT_FLOATS;              // [256][64]
    float* sComb = sm + B_KT_FLOATS + B_Q_FLOATS; // [256][2][4] (m, se, sv, pad)

    const int tid   = threadIdx.x;
    const int r     = blockIdx.x >> 1;
    const int hh    = blockIdx.x & 1;
    const int kbase = r * KPR;
    const int qbase = kbase + hh * 256;

    // K^T load (coalesced gmem, transpose write)
    for (int i = tid; i < KPR * 64; i += 512) {
        int k = i >> 6, d = i & 63;
        sKT[d * B_PAD + k] = g_K[(kbase + k) * 64 + d];
    }
    // Q tile
    for (int i = tid; i < 256 * 64; i += 512)
        sQ[i] = g_Q[qbase * 64 + i];
    __syncthreads();

    const int w = tid >> 5, lane = tid & 31;
    const int g = w >> 1, h = w & 1;      // q-group, k-half

    const float* krow = sKT + h * 256 + lane * 4;

    // this lane's 8 vsum values (order matches score unpack order)
    float vs[8];
    *(float4*)&vs[0] = *(const float4*)&g_vs[kbase + h * 256 + lane * 4];
    *(float4*)&vs[4] = *(const float4*)&g_vs[kbase + h * 256 + 128 + lane * 4];

    const float SC = 1.4426950408889634f * 0.125f;  // log2(e)/sqrt(64)

    for (int p = 0; p < 4; ++p) {
        const int q0 = g * 32 + p * 8;
        const float* Qb = sQ + q0 * 64;

        uint64_t s2[8][4];
        #pragma unroll
        for (int qi = 0; qi < 8; ++qi)
            #pragma unroll
            for (int jp = 0; jp < 4; ++jp) s2[qi][jp] = 0ull;

        #pragma unroll 4
        for (int d = 0; d < 64; ++d) {
            const float* kp = krow + d * B_PAD;
            ulonglong2 t0 = *(const ulonglong2*)kp;         // k pairs 0,1
            ulonglong2 t1 = *(const ulonglong2*)(kp + 128); // k pairs 2,3
            #pragma unroll
            for (int qi = 0; qi < 8; ++qi) {
                uint64_t qd = splat2(Qb[qi * 64 + d]);      // broadcast LDS
                ffma2(s2[qi][0], qd, t0.x);
                ffma2(s2[qi][1], qd, t0.y);
                ffma2(s2[qi][2], qd, t1.x);
                ffma2(s2[qi][3], qd, t1.y);
            }
        }

        // partial softmax over this warp's 256 k
        #pragma unroll
        for (int qi = 0; qi < 8; ++qi) {
            float sc[8];
            #pragma unroll
            for (int jp = 0; jp < 4; ++jp) {
                sc[2 * jp]     = lo32(s2[qi][jp]);
                sc[2 * jp + 1] = hi32(s2[qi][jp]);
            }
            float m = sc[0];
            #pragma unroll
            for (int kk = 1; kk < 8; ++kk) m = fmaxf(m, sc[kk]);
            #pragma unroll
            for (int o = 16; o > 0; o >>= 1)
                m = fmaxf(m, __shfl_xor_sync(0xffffffffu, m, o));

            float se = 0.f, sv = 0.f;
            #pragma unroll
            for (int kk = 0; kk < 8; ++kk) {
                float e = exp2f((sc[kk] - m) * SC);
                se += e;
                sv += e * vs[kk];
            }
            #pragma unroll
            for (int o = 16; o > 0; o >>= 1) {
                se += __shfl_xor_sync(0xffffffffu, se, o);
                sv += __shfl_xor_sync(0xffffffffu, sv, o);
            }
            if (lane == 0) {
                float* c = sComb + ((q0 + qi) * 2 + h) * 4;
                c[0] = m; c[1] = se; c[2] = sv;
            }
        }
    }
    __syncthreads();

    // combine the two k-halves per q row (threads 0..255)
    if (tid < 256) {
        const float* c0 = sComb + (tid * 2 + 0) * 4;
        const float* c1 = sComb + (tid * 2 + 1) * 4;
        float m0 = c0[0], se0 = c0[1], sv0 = c0[2];
        float m1 = c1[0], se1 = c1[1], sv1 = c1[2];
        float M  = fmaxf(m0, m1);
        float f0 = exp2f((m0 - M) * SC);
        float f1 = exp2f((m1 - M) * SC);
        out[qbase + tid] = (sv0 * f0 + sv1 * f1) / (se0 * f0 + se1 * f1);
    }
}

// ---------------------------------------------------------------------------
// Launch
// ---------------------------------------------------------------------------
extern "C" void kernel_launch(void* const* d_in, const int* in_sizes, int n_in,
                              void* d_out, int out_size)
{
    const float* power   = (const float*)d_in[0];
    const int*   ele_idx = (const int*)  d_in[1];
    // d_in[2] = range_indices (unused by reference)
    const int*   azi_idx = (const int*)  d_in[3];
    const float* ele_tab = (const float*)d_in[4];
    const float* azi_tab = (const float*)d_in[5];
    const float* Wq      = (const float*)d_in[6];
    const float* bq      = (const float*)d_in[7];
    const float* Wk      = (const float*)d_in[8];
    const float* bk      = (const float*)d_in[9];
    const float* Wv      = (const float*)d_in[10];
    const float* bv      = (const float*)d_in[11];
    float* out = (float*)d_out;

    cudaFuncSetAttribute(qkv_kernel, cudaFuncAttributeMaxDynamicSharedMemorySize, A_SMEM_BYTES);
    cudaFuncSetAttribute(attn_kernel, cudaFuncAttributeMaxDynamicSharedMemorySize, B_SMEM_BYTES);

    qkv_kernel<<<NROWS / A_ROWS, 256, A_SMEM_BYTES>>>(
        power, ele_idx, azi_idx, ele_tab, azi_tab, Wq, bq, Wk, bk, Wv, bv);
    attn_kernel<<<NUM_RANGES * 2, 512, B_SMEM_BYTES>>>(out);
}

// round 5
// speedup vs baseline: 3.1430x; 1.4855x over previous
#include <cuda_runtime.h>
#include <cuda_bf16.h>
#include <math.h>
#include <stdint.h>

#define NUM_RANGES 256
#define KPR 512
#define DOPPLER 64
#define EMBED 16
#define IN_DIM 96
#define NROWS (NUM_RANGES * KPR)   // 131072

// Scratch (static device allocations are permitted)
__device__ __nv_bfloat16 g_Qh[NROWS * 64];
__device__ __nv_bfloat16 g_Ql[NROWS * 64];
__device__ __nv_bfloat16 g_Kh[NROWS * 64];
__device__ __nv_bfloat16 g_Kl[NROWS * 64];
__device__ float g_vs[NROWS];

// ---------------- packed fp32x2 helpers (Blackwell FFMA2) -------------------
__device__ __forceinline__ uint64_t splat2(float x) {
    uint64_t r; asm("mov.b64 %0, {%1, %1};" : "=l"(r) : "f"(x)); return r;
}
__device__ __forceinline__ void ffma2(uint64_t& d, uint64_t a, uint64_t b) {
    asm("fma.rn.f32x2 %0, %1, %2, %0;" : "+l"(d) : "l"(a), "l"(b));
}
__device__ __forceinline__ float lo32(uint64_t v) {
    return __uint_as_float((unsigned)(v & 0xffffffffu));
}
__device__ __forceinline__ float hi32(uint64_t v) {
    return __uint_as_float((unsigned)(v >> 32));
}

// ---------------- mma.sync / ldmatrix helpers (sm_80+ PTX, sm_103-safe) -----
__device__ __forceinline__ unsigned smem_u32(const void* p) {
    unsigned a;
    asm("{ .reg .u64 t; cvta.to.shared.u64 t, %1; cvt.u32.u64 %0, t; }" : "=r"(a) : "l"(p));
    return a;
}
__device__ __forceinline__ void ldsm_x4(uint32_t* r, unsigned addr) {
    asm volatile("ldmatrix.sync.aligned.m8n8.x4.shared.b16 {%0,%1,%2,%3}, [%4];"
                 : "=r"(r[0]), "=r"(r[1]), "=r"(r[2]), "=r"(r[3]) : "r"(addr));
}
__device__ __forceinline__ void mma_bf16(float* c, const uint32_t* a, const uint32_t* b) {
    asm volatile("mma.sync.aligned.m16n8k16.row.col.f32.bf16.bf16.f32 "
                 "{%0,%1,%2,%3}, {%4,%5,%6,%7}, {%8,%9}, {%0,%1,%2,%3};"
                 : "+f"(c[0]), "+f"(c[1]), "+f"(c[2]), "+f"(c[3])
                 : "r"(a[0]), "r"(a[1]), "r"(a[2]), "r"(a[3]), "r"(b[0]), "r"(b[1]));
}
__device__ __forceinline__ float ex2(float x) {
    float y; asm("ex2.approx.f32 %0, %1;" : "=f"(y) : "f"(x)); return y;
}

// ---------------------------------------------------------------------------
// Kernel A: fused gather + QK projection (+ vsum), FFMA2 mainloop.
// Epilogue writes bf16 hi/lo split of Q (pre-scaled by log2(e)/8) and K.
// ---------------------------------------------------------------------------
#define A_ROWS 128
#define A_PAD 132
#define A_SMEM_FLOATS (2 * 96 * A_PAD + 96 + 128 + 4)
#define A_SMEM_BYTES (A_SMEM_FLOATS * 4)
#define SCQ 0.1803368801111244f   // log2(e) / sqrt(64)

__global__ void __launch_bounds__(256, 2) qkv_kernel(
    const float* __restrict__ power, const int* __restrict__ ele_idx,
    const int* __restrict__ azi_idx, const float* __restrict__ ele_tab,
    const float* __restrict__ azi_tab,
    const float* __restrict__ Wq, const float* __restrict__ bq,
    const float* __restrict__ Wk, const float* __restrict__ bk,
    const float* __restrict__ Wv, const float* __restrict__ bv)
{
    extern __shared__ float sm[];
    float* sX   = sm;                    // [96][A_PAD]  x^T (f-major)
    float* sW   = sm + 96 * A_PAD;       // [96][A_PAD]  W^T (f-major)
    float* sWv  = sm + 2 * 96 * A_PAD;   // [96]
    float* sB   = sWv + 96;              // [128] bq|bk
    float* sBvs = sB + 128;              // [1]

    const int tid  = threadIdx.x;
    const int row0 = blockIdx.x * A_ROWS;

    for (int i = tid; i < A_ROWS * DOPPLER; i += 256) {
        int r = i >> 6, f = i & 63;
        sX[f * A_PAD + r] = power[(row0 + r) * DOPPLER + f];
    }
    for (int i = tid; i < A_ROWS * 2 * EMBED; i += 256) {
        int r = i >> 5, e = i & 31;
        int row = row0 + r;
        float v; int f;
        if (e < EMBED) { v = ele_tab[ele_idx[row] * EMBED + e];          f = 64 + e; }
        else           { v = azi_tab[azi_idx[row] * EMBED + (e - EMBED)]; f = 80 + (e - EMBED); }
        sX[f * A_PAD + r] = v;
    }
    for (int i = tid; i < 64 * 96; i += 256) {
        int d = i / 96, f = i % 96;
        sW[f * A_PAD + d]      = Wq[i];
        sW[f * A_PAD + 64 + d] = Wk[i];
    }
    if (tid < 96) {
        float s = 0.f;
        #pragma unroll 8
        for (int d = 0; d < 64; ++d) s += Wv[d * 96 + tid];
        sWv[tid] = s;
    }
    if (tid < 64)       sB[tid] = bq[tid];
    else if (tid < 128) sB[tid] = bk[tid - 64];
    if (tid == 0) {
        float s = 0.f;
        #pragma unroll 8
        for (int d = 0; d < 64; ++d) s += bv[d];
        *sBvs = s;
    }
    __syncthreads();

    if (tid < 128) {
        float acc = *sBvs;
        #pragma unroll 4
        for (int f = 0; f < 96; ++f) acc += sX[f * A_PAD + tid] * sWv[f];
        g_vs[row0 + tid] = acc;
    }

    // 128x128 register-blocked GEMM with packed FFMA2 (8 rows x 4 col-pairs)
    const int ty = tid >> 4, tx = tid & 15;
    uint64_t acc2[8][4];
    #pragma unroll
    for (int i = 0; i < 8; ++i)
        #pragma unroll
        for (int j = 0; j < 4; ++j) acc2[i][j] = 0ull;

    #pragma unroll 2
    for (int f = 0; f < 96; ++f) {
        const float4* xr = (const float4*)(sX + f * A_PAD);
        float4 a0 = xr[ty * 2], a1 = xr[ty * 2 + 1];
        float a[8] = {a0.x, a0.y, a0.z, a0.w, a1.x, a1.y, a1.z, a1.w};
        const ulonglong2* wr = (const ulonglong2*)(sW + f * A_PAD + tx * 8);
        ulonglong2 b0 = wr[0], b1 = wr[1];
        uint64_t bp[4] = {b0.x, b0.y, b1.x, b1.y};
        #pragma unroll
        for (int i = 0; i < 8; ++i) {
            uint64_t av = splat2(a[i]);
            #pragma unroll
            for (int jp = 0; jp < 4; ++jp) ffma2(acc2[i][jp], av, bp[jp]);
        }
    }

    // epilogue: unpack, add bias, scale (Q only), bf16 hi/lo split, store
    const int cbase = tx * 8;
    const bool isQ = (tx < 8);
    const int cc = isQ ? cbase : (cbase - 64);
    __nv_bfloat16* gh = isQ ? g_Qh : g_Kh;
    __nv_bfloat16* gl = isQ ? g_Ql : g_Kl;
    const float scl = isQ ? SCQ : 1.0f;
    float bb[8];
    #pragma unroll
    for (int j = 0; j < 8; ++j) bb[j] = sB[cbase + j];

    #pragma unroll
    for (int i = 0; i < 8; ++i) {
        int row = row0 + ty * 8 + i;
        float v[8];
        v[0] = (lo32(acc2[i][0]) + bb[0]) * scl;
        v[1] = (hi32(acc2[i][0]) + bb[1]) * scl;
        v[2] = (lo32(acc2[i][1]) + bb[2]) * scl;
        v[3] = (hi32(acc2[i][1]) + bb[3]) * scl;
        v[4] = (lo32(acc2[i][2]) + bb[4]) * scl;
        v[5] = (hi32(acc2[i][2]) + bb[5]) * scl;
        v[6] = (lo32(acc2[i][3]) + bb[6]) * scl;
        v[7] = (hi32(acc2[i][3]) + bb[7]) * scl;
        unsigned hw[4], lw[4];
        #pragma unroll
        for (int j = 0; j < 4; ++j) {
            float a = v[2 * j], b = v[2 * j + 1];
            __nv_bfloat16 ha = __float2bfloat16_rn(a);
            __nv_bfloat16 hb = __float2bfloat16_rn(b);
            __nv_bfloat16 la = __float2bfloat16_rn(a - __bfloat162float(ha));
            __nv_bfloat16 lb = __float2bfloat16_rn(b - __bfloat162float(hb));
            hw[j] = (unsigned)__bfloat16_as_ushort(ha) | ((unsigned)__bfloat16_as_ushort(hb) << 16);
            lw[j] = (unsigned)__bfloat16_as_ushort(la) | ((unsigned)__bfloat16_as_ushort(lb) << 16);
        }
        *(uint4*)&gh[(size_t)row * 64 + cc] = make_uint4(hw[0], hw[1], hw[2], hw[3]);
        *(uint4*)&gl[(size_t)row * 64 + cc] = make_uint4(lw[0], lw[1], lw[2], lw[3]);
    }
}

// ---------------------------------------------------------------------------
// Kernel B: mma.sync bf16-split attention.
// CTA = 128 q x 512 k (grid = 256 ranges x 4 q-blocks), 256 threads (8 warps).
// Each warp: 16 q rows x all 512 k. A-frags (Qh,Ql) resident in registers.
// scores = Qh*Kh + Qh*Kl + Ql*Kh (Q pre-scaled to log2 units).
// Per 64-k tile: exp2 + se/sv accumulation in C-frag layout; quad shfl reduce.
// smem rows padded to 72 bf16 (144 B): ldmatrix 8-row phases conflict-free.
// ---------------------------------------------------------------------------
#define QS 72
#define S_QH 0
#define S_QL (S_QH + 128 * QS * 2)          // 18432
#define S_KH (S_QL + 128 * QS * 2)          // 36864
#define S_KL (S_KH + 512 * QS * 2)          // 110592
#define S_VS (S_KL + 512 * QS * 2)          // 184320
#define B_SMEM_BYTES (S_VS + 512 * 4)       // 186368

__global__ void __launch_bounds__(256, 1) attn_mma_kernel(float* __restrict__ out)
{
    extern __shared__ char smem[];
    const unsigned sbase = smem_u32(smem);
    const int tid = threadIdx.x;
    const int r = blockIdx.x >> 2, qb = blockIdx.x & 3;
    const int kbase = r * KPR;
    const int qrow0 = kbase + qb * 128;

    // ---- load Q (hi/lo), K (hi/lo), vsum into smem ----
    {
        const uint4* Qh4 = (const uint4*)g_Qh;
        const uint4* Ql4 = (const uint4*)g_Ql;
        for (int i = tid; i < 1024; i += 256) {           // 128 rows x 8 chunks
            int row = i >> 3, c = i & 7;
            unsigned off = row * QS * 2 + c * 16;
            size_t g = (size_t)(qrow0 + row) * 8 + c;
            *(uint4*)(smem + S_QH + off) = Qh4[g];
            *(uint4*)(smem + S_QL + off) = Ql4[g];
        }
        const uint4* Kh4 = (const uint4*)g_Kh;
        const uint4* Kl4 = (const uint4*)g_Kl;
        for (int i = tid; i < 4096; i += 256) {           // 512 rows x 8 chunks
            int row = i >> 3, c = i & 7;
            unsigned off = row * QS * 2 + c * 16;
            size_t g = (size_t)(kbase + row) * 8 + c;
            *(uint4*)(smem + S_KH + off) = Kh4[g];
            *(uint4*)(smem + S_KL + off) = Kl4[g];
        }
        for (int i = tid; i < 512; i += 256)
            *(float*)(smem + S_VS + i * 4) = g_vs[kbase + i];
    }
    __syncthreads();

    const int w = tid >> 5, lane = tid & 31;
    const int qr = w * 16;

    // ---- resident A fragments (Qh, Ql), 4 d-chunks ----
    uint32_t Ah[4][4], Al[4][4];
    {
        int arow = qr + (lane & 15);
        int acol = (lane >> 4) * 8;
        #pragma unroll
        for (int dc = 0; dc < 4; ++dc) {
            unsigned off = (unsigned)(arow * QS + dc * 16 + acol) * 2;
            ldsm_x4(Ah[dc], sbase + S_QH + off);
            ldsm_x4(Al[dc], sbase + S_QL + off);
        }
    }

    float se0 = 0.f, sv0 = 0.f, se1 = 0.f, sv1 = 0.f;
    const int brow = (lane & 7) + ((lane >> 4) << 3);
    const int bcol = ((lane >> 3) & 1) * 8;
    const float* vsp = (const float*)(smem + S_VS);
    const int c0off = 2 * (lane & 3);

    for (int kt = 0; kt < 8; ++kt) {
        float C[8][4];
        #pragma unroll
        for (int nt = 0; nt < 8; ++nt)
            #pragma unroll
            for (int j = 0; j < 4; ++j) C[nt][j] = 0.f;

        #pragma unroll
        for (int dc = 0; dc < 4; ++dc) {
            #pragma unroll
            for (int nt2 = 0; nt2 < 4; ++nt2) {
                int n0 = kt * 64 + nt2 * 16;
                unsigned off = (unsigned)((n0 + brow) * QS + dc * 16 + bcol) * 2;
                uint32_t Bh[4], Bl[4];
                ldsm_x4(Bh, sbase + S_KH + off);
                ldsm_x4(Bl, sbase + S_KL + off);
                mma_bf16(C[nt2 * 2],     Ah[dc], Bh);
                mma_bf16(C[nt2 * 2 + 1], Ah[dc], Bh + 2);
                mma_bf16(C[nt2 * 2],     Ah[dc], Bl);
                mma_bf16(C[nt2 * 2 + 1], Ah[dc], Bl + 2);
                mma_bf16(C[nt2 * 2],     Al[dc], Bh);
                mma_bf16(C[nt2 * 2 + 1], Al[dc], Bh + 2);
            }
        }

        // epilogue for this 64-k tile (scores already in log2 units)
        #pragma unroll
        for (int nt = 0; nt < 8; ++nt) {
            int col0 = kt * 64 + nt * 8 + c0off;
            float2 vv = *(const float2*)(vsp + col0);
            float e0 = ex2(C[nt][0]);
            float e1 = ex2(C[nt][1]);
            float e2 = ex2(C[nt][2]);
            float e3 = ex2(C[nt][3]);
            se0 += e0 + e1; sv0 += e0 * vv.x + e1 * vv.y;
            se1 += e2 + e3; sv1 += e2 * vv.x + e3 * vv.y;
        }
    }

    // reduce within quad (lanes sharing row group lane>>2)
    #pragma unroll
    for (int o = 1; o <= 2; o <<= 1) {
        se0 += __shfl_xor_sync(0xffffffffu, se0, o);
        sv0 += __shfl_xor_sync(0xffffffffu, sv0, o);
        se1 += __shfl_xor_sync(0xffffffffu, se1, o);
        sv1 += __shfl_xor_sync(0xffffffffu, sv1, o);
    }
    if ((lane & 3) == 0) {
        int row = qrow0 + qr + (lane >> 2);
        out[row]     = sv0 / se0;
        out[row + 8] = sv1 / se1;
    }
}

// ---------------------------------------------------------------------------
// Launch
// ---------------------------------------------------------------------------
extern "C" void kernel_launch(void* const* d_in, const int* in_sizes, int n_in,
                              void* d_out, int out_size)
{
    const float* power   = (const float*)d_in[0];
    const int*   ele_idx = (const int*)  d_in[1];
    // d_in[2] = range_indices (unused by reference)
    const int*   azi_idx = (const int*)  d_in[3];
    const float* ele_tab = (const float*)d_in[4];
    const float* azi_tab = (const float*)d_in[5];
    const float* Wq      = (const float*)d_in[6];
    const float* bq      = (const float*)d_in[7];
    const float* Wk      = (const float*)d_in[8];
    const float* bk      = (const float*)d_in[9];
    const float* Wv      = (const float*)d_in[10];
    const float* bv      = (const float*)d_in[11];
    float* out = (float*)d_out;

    cudaFuncSetAttribute(qkv_kernel, cudaFuncAttributeMaxDynamicSharedMemorySize, A_SMEM_BYTES);
    cudaFuncSetAttribute(attn_mma_kernel, cudaFuncAttributeMaxDynamicSharedMemorySize, B_SMEM_BYTES);

    qkv_kernel<<<NROWS / A_ROWS, 256, A_SMEM_BYTES>>>(
        power, ele_idx, azi_idx, ele_tab, azi_tab, Wq, bq, Wk, bk, Wv, bv);
    attn_mma_kernel<<<NUM_RANGES * 4, 256, B_SMEM_BYTES>>>(out);
}

// round 6
// speedup vs baseline: 3.6597x; 1.1644x over previous
#include <cuda_runtime.h>
#include <cuda_bf16.h>
#include <math.h>
#include <stdint.h>

#define NUM_RANGES 256
#define KPR 512
#define DOPPLER 64
#define EMBED 16
#define IN_DIM 96
#define NROWS (NUM_RANGES * KPR)   // 131072

// Scratch (static device allocations are permitted)
__device__ __nv_bfloat16 g_Qh[NROWS * 64];
__device__ __nv_bfloat16 g_Ql[NROWS * 64];
__device__ __nv_bfloat16 g_Kh[NROWS * 64];
__device__ __nv_bfloat16 g_Kl[NROWS * 64];
__device__ float g_vs[NROWS];

// ---------------- mma.sync / ldmatrix helpers (sm_80+ PTX, sm_103-safe) -----
__device__ __forceinline__ unsigned smem_u32(const void* p) {
    unsigned a;
    asm("{ .reg .u64 t; cvta.to.shared.u64 t, %1; cvt.u32.u64 %0, t; }" : "=r"(a) : "l"(p));
    return a;
}
__device__ __forceinline__ void ldsm_x4(uint32_t* r, unsigned addr) {
    asm volatile("ldmatrix.sync.aligned.m8n8.x4.shared.b16 {%0,%1,%2,%3}, [%4];"
                 : "=r"(r[0]), "=r"(r[1]), "=r"(r[2]), "=r"(r[3]) : "r"(addr));
}
__device__ __forceinline__ void mma_bf16(float* c, const uint32_t* a, const uint32_t* b) {
    asm volatile("mma.sync.aligned.m16n8k16.row.col.f32.bf16.bf16.f32 "
                 "{%0,%1,%2,%3}, {%4,%5,%6,%7}, {%8,%9}, {%0,%1,%2,%3};"
                 : "+f"(c[0]), "+f"(c[1]), "+f"(c[2]), "+f"(c[3])
                 : "r"(a[0]), "r"(a[1]), "r"(a[2]), "r"(a[3]), "r"(b[0]), "r"(b[1]));
}
__device__ __forceinline__ float ex2(float x) {
    float y; asm("ex2.approx.f32 %0, %1;" : "=f"(y) : "f"(x)); return y;
}
__device__ __forceinline__ void bsplit(float v, __nv_bfloat16& h, __nv_bfloat16& l) {
    h = __float2bfloat16_rn(v);
    l = __float2bfloat16_rn(v - __bfloat162float(h));
}

#define SCQ 0.1803368801111244f   // log2(e) / sqrt(64)

// ---------------------------------------------------------------------------
// Kernel A: fused gather + QK projection via mma.sync (bf16 hi/lo split on
// both x and W: 3-term product). CTA = 128 rows x 128 outs x 96, 256 thr.
// Epilogue: +bias, Q cols scaled by SCQ, bf16 hi/lo split, packed stores.
// vsum computed from (xh+xl) per row.
// ---------------------------------------------------------------------------
#define QP 104                              // padded bf16 row (96->104): ldsm conflict-free
#define AX_H 0
#define AX_L (AX_H + 128 * QP * 2)          // 26624
#define AW_H (AX_L + 128 * QP * 2)          // 53248
#define AW_L (AW_H + 128 * QP * 2)          // 79872
#define A_WV (AW_L + 128 * QP * 2)          // 106496  float[96]
#define A_BB (A_WV + 96 * 4)                // 106880  float[128]
#define A_BVS (A_BB + 128 * 4)              // 107392  float[1]
#define A_SMEM_BYTES (A_BVS + 128)          // 107520

__global__ void __launch_bounds__(256, 2) qkv_mma_kernel(
    const float* __restrict__ power, const int* __restrict__ ele_idx,
    const int* __restrict__ azi_idx, const float* __restrict__ ele_tab,
    const float* __restrict__ azi_tab,
    const float* __restrict__ Wq, const float* __restrict__ bq,
    const float* __restrict__ Wk, const float* __restrict__ bk,
    const float* __restrict__ Wv, const float* __restrict__ bv)
{
    extern __shared__ char smem[];
    const unsigned sbase = smem_u32(smem);
    __nv_bfloat16* xh = (__nv_bfloat16*)(smem + AX_H);
    __nv_bfloat16* xl = (__nv_bfloat16*)(smem + AX_L);
    __nv_bfloat16* wh = (__nv_bfloat16*)(smem + AW_H);
    __nv_bfloat16* wl = (__nv_bfloat16*)(smem + AW_L);
    float* sWv  = (float*)(smem + A_WV);
    float* sB   = (float*)(smem + A_BB);
    float* sBvs = (float*)(smem + A_BVS);

    const int tid  = threadIdx.x;
    const int row0 = blockIdx.x * 128;

    // gather + split x
    for (int i = tid; i < 128 * DOPPLER; i += 256) {
        int r = i >> 6, f = i & 63;
        __nv_bfloat16 h, l;
        bsplit(power[(size_t)(row0 + r) * DOPPLER + f], h, l);
        xh[r * QP + f] = h; xl[r * QP + f] = l;
    }
    for (int i = tid; i < 128 * 2 * EMBED; i += 256) {
        int r = i >> 5, e = i & 31;
        int row = row0 + r;
        float v; int f;
        if (e < EMBED) { v = ele_tab[ele_idx[row] * EMBED + e];          f = 64 + e; }
        else           { v = azi_tab[azi_idx[row] * EMBED + (e - EMBED)]; f = 80 + (e - EMBED); }
        __nv_bfloat16 h, l; bsplit(v, h, l);
        xh[r * QP + f] = h; xl[r * QP + f] = l;
    }
    // weights: rows 0..63 = Wq, 64..127 = Wk
    for (int i = tid; i < 64 * 96; i += 256) {
        int d = i / 96, f = i % 96;
        __nv_bfloat16 h, l;
        bsplit(Wq[i], h, l); wh[d * QP + f] = h;        wl[d * QP + f] = l;
        bsplit(Wk[i], h, l); wh[(64 + d) * QP + f] = h; wl[(64 + d) * QP + f] = l;
    }
    if (tid < 96) {
        float s = 0.f;
        #pragma unroll 8
        for (int d = 0; d < 64; ++d) s += Wv[d * 96 + tid];
        sWv[tid] = s;
    }
    if (tid < 64)       sB[tid] = bq[tid];
    else if (tid < 128) sB[tid] = bk[tid - 64];
    if (tid == 0) {
        float s = 0.f;
        #pragma unroll 8
        for (int d = 0; d < 64; ++d) s += bv[d];
        *sBvs = s;
    }
    __syncthreads();

    if (tid < 128) {
        float acc = *sBvs;
        #pragma unroll 4
        for (int f = 0; f < 96; ++f)
            acc += (__bfloat162float(xh[tid * QP + f]) + __bfloat162float(xl[tid * QP + f])) * sWv[f];
        g_vs[row0 + tid] = acc;
    }

    // ---- MMA: warp w = rows qr..qr+15, all 128 outs, K=96 (6 chunks) ----
    const int w = tid >> 5, lane = tid & 31;
    const int qr = w * 16;
    const int arow = qr + (lane & 15);
    const int acol = (lane >> 4) * 8;
    const int brow = (lane & 7) + ((lane >> 4) << 3);
    const int bcol = ((lane >> 3) & 1) * 8;

    float C[16][4];
    #pragma unroll
    for (int nt = 0; nt < 16; ++nt)
        #pragma unroll
        for (int j = 0; j < 4; ++j) C[nt][j] = 0.f;

    #pragma unroll
    for (int dc = 0; dc < 6; ++dc) {
        uint32_t Ah[4], Al[4];
        unsigned aoff = (unsigned)(arow * QP + dc * 16 + acol) * 2;
        ldsm_x4(Ah, sbase + AX_H + aoff);
        ldsm_x4(Al, sbase + AX_L + aoff);
        #pragma unroll
        for (int nt2 = 0; nt2 < 8; ++nt2) {
            unsigned boff = (unsigned)((nt2 * 16 + brow) * QP + dc * 16 + bcol) * 2;
            uint32_t Bh[4], Bl[4];
            ldsm_x4(Bh, sbase + AW_H + boff);
            ldsm_x4(Bl, sbase + AW_L + boff);
            mma_bf16(C[nt2 * 2],     Ah, Bh);
            mma_bf16(C[nt2 * 2 + 1], Ah, Bh + 2);
            mma_bf16(C[nt2 * 2],     Ah, Bl);
            mma_bf16(C[nt2 * 2 + 1], Ah, Bl + 2);
            mma_bf16(C[nt2 * 2],     Al, Bh);
            mma_bf16(C[nt2 * 2 + 1], Al, Bh + 2);
        }
    }

    // ---- epilogue: bias + scale + hi/lo split + packed bf16x2 stores ----
    const int r0 = row0 + qr + (lane >> 2);
    #pragma unroll
    for (int nt = 0; nt < 16; ++nt) {
        int cb = nt * 8 + (lane & 3) * 2;
        bool isQ = (nt < 8);
        float scl = isQ ? SCQ : 1.0f;
        int cc = isQ ? cb : (cb - 64);
        __nv_bfloat16* gh = isQ ? g_Qh : g_Kh;
        __nv_bfloat16* gl = isQ ? g_Ql : g_Kl;
        float b0 = sB[cb], b1 = sB[cb + 1];
        float v00 = (C[nt][0] + b0) * scl, v01 = (C[nt][1] + b1) * scl;
        float v10 = (C[nt][2] + b0) * scl, v11 = (C[nt][3] + b1) * scl;
        __nv_bfloat16 h0, l0, h1, l1;
        bsplit(v00, h0, l0); bsplit(v01, h1, l1);
        *(unsigned*)&gh[(size_t)r0 * 64 + cc] =
            (unsigned)__bfloat16_as_ushort(h0) | ((unsigned)__bfloat16_as_ushort(h1) << 16);
        *(unsigned*)&gl[(size_t)r0 * 64 + cc] =
            (unsigned)__bfloat16_as_ushort(l0) | ((unsigned)__bfloat16_as_ushort(l1) << 16);
        bsplit(v10, h0, l0); bsplit(v11, h1, l1);
        *(unsigned*)&gh[(size_t)(r0 + 8) * 64 + cc] =
            (unsigned)__bfloat16_as_ushort(h0) | ((unsigned)__bfloat16_as_ushort(h1) << 16);
        *(unsigned*)&gl[(size_t)(r0 + 8) * 64 + cc] =
            (unsigned)__bfloat16_as_ushort(l0) | ((unsigned)__bfloat16_as_ushort(l1) << 16);
    }
}

// ---------------------------------------------------------------------------
// Kernel B: mma.sync bf16-split attention, 512 threads (16 warps).
// CTA = 128 q x 512 k (grid = 1024). Warp (g,h): 16 q rows (g), k-half h (256 k).
// Partial se/sv merged in smem (valid: no max-subtract, shared zero offset).
// ---------------------------------------------------------------------------
#define QS 72
#define S_QH 0
#define S_QL (S_QH + 128 * QS * 2)          // 18432
#define S_KH (S_QL + 128 * QS * 2)          // 36864
#define S_KL (S_KH + 512 * QS * 2)          // 110592
#define S_VS (S_KL + 512 * QS * 2)          // 184320
#define S_COMB (S_VS + 512 * 4)             // 186368
#define B_SMEM_BYTES (S_COMB + 128 * 2 * 8) // 188416

__global__ void __launch_bounds__(512, 1) attn_mma_kernel(float* __restrict__ out)
{
    extern __shared__ char smem[];
    const unsigned sbase = smem_u32(smem);
    const int tid = threadIdx.x;
    const int r = blockIdx.x >> 2, qb = blockIdx.x & 3;
    const int kbase = r * KPR;
    const int qrow0 = kbase + qb * 128;

    // ---- load Q (hi/lo), K (hi/lo), vsum into smem ----
    {
        const uint4* Qh4 = (const uint4*)g_Qh;
        const uint4* Ql4 = (const uint4*)g_Ql;
        for (int i = tid; i < 1024; i += 512) {
            int row = i >> 3, c = i & 7;
            unsigned off = row * QS * 2 + c * 16;
            size_t g = (size_t)(qrow0 + row) * 8 + c;
            *(uint4*)(smem + S_QH + off) = Qh4[g];
            *(uint4*)(smem + S_QL + off) = Ql4[g];
        }
        const uint4* Kh4 = (const uint4*)g_Kh;
        const uint4* Kl4 = (const uint4*)g_Kl;
        for (int i = tid; i < 4096; i += 512) {
            int row = i >> 3, c = i & 7;
            unsigned off = row * QS * 2 + c * 16;
            size_t g = (size_t)(kbase + row) * 8 + c;
            *(uint4*)(smem + S_KH + off) = Kh4[g];
            *(uint4*)(smem + S_KL + off) = Kl4[g];
        }
        for (int i = tid; i < 512; i += 512)
            *(float*)(smem + S_VS + i * 4) = g_vs[kbase + i];
    }
    __syncthreads();

    const int w = tid >> 5, lane = tid & 31;
    const int g = w >> 1, h = w & 1;
    const int qr = g * 16;
    const int kofs = h * 256;

    // ---- resident A fragments (Qh, Ql), 4 d-chunks ----
    uint32_t Ah[4][4], Al[4][4];
    {
        int arow = qr + (lane & 15);
        int acol = (lane >> 4) * 8;
        #pragma unroll
        for (int dc = 0; dc < 4; ++dc) {
            unsigned off = (unsigned)(arow * QS + dc * 16 + acol) * 2;
            ldsm_x4(Ah[dc], sbase + S_QH + off);
            ldsm_x4(Al[dc], sbase + S_QL + off);
        }
    }

    float se0 = 0.f, sv0 = 0.f, se1 = 0.f, sv1 = 0.f;
    const int brow = (lane & 7) + ((lane >> 4) << 3);
    const int bcol = ((lane >> 3) & 1) * 8;
    const float* vsp = (const float*)(smem + S_VS);
    const int c0off = 2 * (lane & 3);

    for (int kt = 0; kt < 4; ++kt) {
        float C[8][4];
        #pragma unroll
        for (int nt = 0; nt < 8; ++nt)
            #pragma unroll
            for (int j = 0; j < 4; ++j) C[nt][j] = 0.f;

        #pragma unroll
        for (int dc = 0; dc < 4; ++dc) {
            #pragma unroll
            for (int nt2 = 0; nt2 < 4; ++nt2) {
                int n0 = kofs + kt * 64 + nt2 * 16;
                unsigned off = (unsigned)((n0 + brow) * QS + dc * 16 + bcol) * 2;
                uint32_t Bh[4], Bl[4];
                ldsm_x4(Bh, sbase + S_KH + off);
                ldsm_x4(Bl, sbase + S_KL + off);
                mma_bf16(C[nt2 * 2],     Ah[dc], Bh);
                mma_bf16(C[nt2 * 2 + 1], Ah[dc], Bh + 2);
                mma_bf16(C[nt2 * 2],     Ah[dc], Bl);
                mma_bf16(C[nt2 * 2 + 1], Ah[dc], Bl + 2);
                mma_bf16(C[nt2 * 2],     Al[dc], Bh);
                mma_bf16(C[nt2 * 2 + 1], Al[dc], Bh + 2);
            }
        }

        // epilogue for this 64-k tile (scores already in log2 units)
        #pragma unroll
        for (int nt = 0; nt < 8; ++nt) {
            int col0 = kofs + kt * 64 + nt * 8 + c0off;
            float2 vv = *(const float2*)(vsp + col0);
            float e0 = ex2(C[nt][0]);
            float e1 = ex2(C[nt][1]);
            float e2 = ex2(C[nt][2]);
            float e3 = ex2(C[nt][3]);
            se0 += e0 + e1; sv0 += e0 * vv.x + e1 * vv.y;
            se1 += e2 + e3; sv1 += e2 * vv.x + e3 * vv.y;
        }
    }

    // reduce within quad, then write partials for cross-half merge
    #pragma unroll
    for (int o = 1; o <= 2; o <<= 1) {
        se0 += __shfl_xor_sync(0xffffffffu, se0, o);
        sv0 += __shfl_xor_sync(0xffffffffu, sv0, o);
        se1 += __shfl_xor_sync(0xffffffffu, se1, o);
        sv1 += __shfl_xor_sync(0xffffffffu, sv1, o);
    }
    float2* comb = (float2*)(smem + S_COMB);
    if ((lane & 3) == 0) {
        int rl = qr + (lane >> 2);
        comb[rl * 2 + h]       = make_float2(se0, sv0);
        comb[(rl + 8) * 2 + h] = make_float2(se1, sv1);
    }
    __syncthreads();
    if (tid < 128) {
        float2 a = comb[tid * 2], b = comb[tid * 2 + 1];
        out[qrow0 + tid] = (a.y + b.y) / (a.x + b.x);
    }
}

// ---------------------------------------------------------------------------
// Launch
// ---------------------------------------------------------------------------
extern "C" void kernel_launch(void* const* d_in, const int* in_sizes, int n_in,
                              void* d_out, int out_size)
{
    const float* power   = (const float*)d_in[0];
    const int*   ele_idx = (const int*)  d_in[1];
    // d_in[2] = range_indices (unused by reference)
    const int*   azi_idx = (const int*)  d_in[3];
    const float* ele_tab = (const float*)d_in[4];
    const float* azi_tab = (const float*)d_in[5];
    const float* Wq      = (const float*)d_in[6];
    const float* bq      = (const float*)d_in[7];
    const float* Wk      = (const float*)d_in[8];
    const float* bk      = (const float*)d_in[9];
    const float* Wv      = (const float*)d_in[10];
    const float* bv      = (const float*)d_in[11];
    float* out = (float*)d_out;

    cudaFuncSetAttribute(qkv_mma_kernel, cudaFuncAttributeMaxDynamicSharedMemorySize, A_SMEM_BYTES);
    cudaFuncSetAttribute(attn_mma_kernel, cudaFuncAttributeMaxDynamicSharedMemorySize, B_SMEM_BYTES);

    qkv_mma_kernel<<<NROWS / 128, 256, A_SMEM_BYTES>>>(
        power, ele_idx, azi_idx, ele_tab, azi_tab, Wq, bq, Wk, bk, Wv, bv);
    attn_mma_kernel<<<NUM_RANGES * 4, 512, B_SMEM_BYTES>>>(out);
}